// round 6
// baseline (speedup 1.0000x reference)
#include <cuda_runtime.h>
#include <math.h>
#include <stdint.h>

// Problem shape (fixed)
#define BB 4
#define SS 2048
#define DD 1024
#define MM (BB*SS)   // 8192

// ---------------- scratch ----------------
__device__ float g_X [MM*DD];                 // x, tf32-rounded
__device__ float g_Wq[DD*DD];
__device__ float g_Wk[DD*DD];
__device__ float g_Wv[DD*DD];
__device__ float g_Wo[DD*DD];
__device__ float g_Q [MM*DD];
__device__ float g_K [MM*DD];
__device__ float g_Vt[MM*DD];                 // V projected, transposed per batch: [b][d][s]
__device__ float g_S [(long long)BB*SS*SS];   // scores / probs
__device__ float g_A [MM*DD];

// ---------------- helpers ----------------
__device__ __forceinline__ uint32_t smem_u32(const void* p) {
    uint32_t a;
    asm("{ .reg .u64 t; cvta.to.shared.u64 t, %1; cvt.u32.u64 %0, t; }" : "=r"(a) : "l"(p));
    return a;
}
__device__ __forceinline__ void cp16(uint32_t dst, const void* src) {
    asm volatile("cp.async.cg.shared.global [%0], [%1], 16;" :: "r"(dst), "l"(src));
}
#define CP_COMMIT() asm volatile("cp.async.commit_group;" ::: "memory")
#define CP_WAIT1()  asm volatile("cp.async.wait_group 1;"  ::: "memory")

__device__ __forceinline__ float tf32rf(float x) {   // round-to-nearest tf32 (fp32 container)
    float r;
    asm("cvt.rna.tf32.f32 %0, %1;" : "=f"(r) : "f"(x));
    return r;
}

// chunk-swizzled smem offset: row stride 64B (16 floats), 16B chunk rotated by row>>1
#define SWOFF(row, c) ((uint32_t)((row)*64 + ((((c) + ((row)>>1)) & 3) << 4)))

// float2 fragment load: two adjacent tf32 words (logical k = 2w, 2w+1 within 8-k group)
__device__ __forceinline__ uint2 lds_u2(const char* p, int row, int c, int o8) {
    return *(const uint2*)(p + SWOFF(row, c) + o8);
}

#define MMA_TF32(cc, a0, a1, a2, a3, b0, b1) \
    asm volatile("mma.sync.aligned.m16n8k8.row.col.f32.tf32.tf32.f32 " \
        "{%0,%1,%2,%3}, {%4,%5,%6,%7}, {%8,%9}, {%0,%1,%2,%3};" \
        : "+f"((cc)[0]), "+f"((cc)[1]), "+f"((cc)[2]), "+f"((cc)[3]) \
        : "r"(a0), "r"(a1), "r"(a2), "r"(a3), "r"(b0), "r"(b1))

// ================= pre-round x and all weights to tf32 =================
#define NX4 (MM*DD/4)      // 2097152
#define NW4 (DD*DD/4)      // 262144
__global__ void __launch_bounds__(256) preround_all(
    const float4* __restrict__ x,
    const float4* __restrict__ wq, const float4* __restrict__ wk,
    const float4* __restrict__ wv, const float4* __restrict__ wo,
    float4* __restrict__ dx,
    float4* __restrict__ dwq, float4* __restrict__ dwk,
    float4* __restrict__ dwv, float4* __restrict__ dwo)
{
    long long i = (long long)blockIdx.x * blockDim.x + threadIdx.x;
    const float4* s; float4* d; long long off;
    if (i < NX4) { s = x; d = dx; off = i; }
    else {
        long long j = i - NX4;
        int seg = (int)(j / NW4);
        off = j % NW4;
        s = seg == 0 ? wq : seg == 1 ? wk : seg == 2 ? wv : wo;
        d = seg == 0 ? dwq : seg == 1 ? dwk : seg == 2 ? dwv : dwo;
    }
    float4 v = s[off];
    v.x = tf32rf(v.x); v.y = tf32rf(v.y); v.z = tf32rf(v.z); v.w = tf32rf(v.w);
    d[off] = v;
}

// ================= tf32 mma.sync GEMM: C = alpha * A @ B^T (TN) =================
// Operands pre-rounded to tf32 in memory. 128x128 CTA tile, BK=16,
// 3-stage cp.async, 256 threads = 8 warps (2x4), warp tile 64x32.
// Fragment loads are LDS.64 via in-MMA k-permutation (slot w -> k=2w, slot w+4 -> k=2w+1;
// identical permutation on A and B leaves the dot product unchanged).
// mode: 0 plain | 1 causal tile-skip | 2 causal K-trunc + round out
//       | 3 transposed-per-batch + rounded out | 4 fused RoPE + rounded out
#define STAGE 16384           // A 8KB + B 8KB
#define SM_TOTAL (3*STAGE)    // 49152

__global__ void __launch_bounds__(256, 2) gemm_mma(
    const float* __restrict__ A, const float* __restrict__ B, float* __restrict__ C,
    int M, int N, int K,
    long long sA, long long sB, long long sC,
    float alpha, int mode, const int* __restrict__ pos)
{
    extern __shared__ char smem[];
    int bz = blockIdx.z;
    const float* Ab = A + (long long)bz * sA;
    const float* Bb = B + (long long)bz * sB;

    int m0 = blockIdx.y * 128;
    int n0 = blockIdx.x * 128;
    if (mode == 1 && n0 >= m0 + 128) return;
    int Keff  = (mode == 2) ? min(K, m0 + 128) : K;
    int nIter = Keff >> 4;

    int tid = threadIdx.x, wid = tid >> 5, lane = tid & 31;
    int warp_m = wid >> 2, warp_n = wid & 3;
    int g = lane >> 2, w = lane & 3;
    int cw = w >> 1, o8 = (w & 1) * 8;       // chunk sub-index + byte offset for float2 loads
    uint32_t sb = smem_u32(smem);

    // global->smem: thread -> row tid>>1, chunks (tid&1)*2, +1
    int rowL = tid >> 1, cL = (tid & 1) * 2;
    uint32_t dOff0 = SWOFF(rowL, cL);
    uint32_t dOff1 = SWOFF(rowL, cL + 1);
    const float* gAp = Ab + (long long)(m0 + rowL) * K + cL * 4;
    const float* gBp = Bb + (long long)(n0 + rowL) * K + cL * 4;

    float acc[4][4][4];
    #pragma unroll
    for (int i = 0; i < 4; i++)
        #pragma unroll
        for (int j = 0; j < 4; j++)
            #pragma unroll
            for (int q = 0; q < 4; q++) acc[i][j][q] = 0.f;

    #pragma unroll
    for (int s = 0; s < 2; s++) {
        uint32_t base = sb + s * STAGE;
        int k0 = s * 16;
        cp16(base + dOff0,        gAp + k0);
        cp16(base + dOff1,        gAp + k0 + 4);
        cp16(base + 8192 + dOff0, gBp + k0);
        cp16(base + 8192 + dOff1, gBp + k0 + 4);
        CP_COMMIT();
    }

    for (int kt = 0; kt < nIter; kt++) {
        CP_WAIT1();
        __syncthreads();

        const char* pA = smem + (kt % 3) * STAGE;
        const char* pB = pA + 8192;
        #pragma unroll
        for (int ks = 0; ks < 2; ks++) {
            int c = ks * 2 + cw;
            uint32_t af[4][4], bf[4][2];
            #pragma unroll
            for (int mf = 0; mf < 4; mf++) {
                int r = warp_m * 64 + mf * 16 + g;
                uint2 lo = lds_u2(pA, r,     c, o8);
                uint2 hi = lds_u2(pA, r + 8, c, o8);
                af[mf][0] = lo.x; af[mf][1] = hi.x; af[mf][2] = lo.y; af[mf][3] = hi.y;
            }
            #pragma unroll
            for (int nf = 0; nf < 4; nf++) {
                int nr = warp_n * 32 + nf * 8 + g;
                uint2 bv = lds_u2(pB, nr, c, o8);
                bf[nf][0] = bv.x; bf[nf][1] = bv.y;
            }
            #pragma unroll
            for (int mf = 0; mf < 4; mf++)
                #pragma unroll
                for (int nf = 0; nf < 4; nf++)
                    MMA_TF32(acc[mf][nf], af[mf][0], af[mf][1], af[mf][2], af[mf][3],
                             bf[nf][0], bf[nf][1]);
        }

        int nk = kt + 2;
        if (nk < nIter) {
            uint32_t base = sb + (nk % 3) * STAGE;
            int k0 = nk * 16;
            cp16(base + dOff0,        gAp + k0);
            cp16(base + dOff1,        gAp + k0 + 4);
            cp16(base + 8192 + dOff0, gBp + k0);
            cp16(base + 8192 + dOff1, gBp + k0 + 4);
        }
        CP_COMMIT();
    }

    if (mode == 4) {
        // fused RoPE epilogue: col pairs (2i, 2i+1) live in one float2
        bool is64 = (pos[1] == 0);
        #pragma unroll
        for (int mf = 0; mf < 4; mf++) {
            int r0 = m0 + warp_m * 64 + mf * 16 + g;
            int p0 = is64 ? pos[2 * r0] : pos[r0];
            int p1 = is64 ? pos[2 * (r0 + 8)] : pos[r0 + 8];
            #pragma unroll
            for (int nf = 0; nf < 4; nf++) {
                int col = n0 + warp_n * 32 + nf * 8 + w * 2;
                float inv_freq = exp2f((float)col * (-13.28771238f / (float)DD));
                float c0, s0, c1, s1;
                sincosf((float)p0 * inv_freq, &s0, &c0);
                sincosf((float)p1 * inv_freq, &s1, &c1);
                float x1 = acc[mf][nf][0], x2 = acc[mf][nf][1];
                float y1 = acc[mf][nf][2], y2 = acc[mf][nf][3];
                float2 v0 = make_float2(tf32rf(x1 * c0 - x2 * s0), tf32rf(x1 * s0 + x2 * c0));
                float2 v1 = make_float2(tf32rf(y1 * c1 - y2 * s1), tf32rf(y1 * s1 + y2 * c1));
                *(float2*)&C[(long long)r0 * N + col]       = v0;
                *(float2*)&C[(long long)(r0 + 8) * N + col] = v1;
            }
        }
    } else if (mode != 3) {
        bool rnd = (mode == 2);
        float* Cb = C + (long long)bz * sC;
        #pragma unroll
        for (int mf = 0; mf < 4; mf++) {
            int r0 = m0 + warp_m * 64 + mf * 16 + g;
            #pragma unroll
            for (int nf = 0; nf < 4; nf++) {
                int col = n0 + warp_n * 32 + nf * 8 + w * 2;
                float2 v0 = make_float2(acc[mf][nf][0] * alpha, acc[mf][nf][1] * alpha);
                float2 v1 = make_float2(acc[mf][nf][2] * alpha, acc[mf][nf][3] * alpha);
                if (rnd) {
                    v0.x = tf32rf(v0.x); v0.y = tf32rf(v0.y);
                    v1.x = tf32rf(v1.x); v1.y = tf32rf(v1.y);
                }
                *(float2*)&Cb[(long long)r0 * N + col]       = v0;
                *(float2*)&Cb[(long long)(r0 + 8) * N + col] = v1;
            }
        }
    } else {
        // transposed epilogue: stage 128x32 column block through smem, store d-major, rounded
        float* Ts = (float*)smem;                 // [128][33]
        int b = m0 / SS;
        int srow0 = m0 % SS;
        float* Cb = C + (long long)b * sC;        // sC = DD*SS
        #pragma unroll
        for (int nc = 0; nc < 4; nc++) {
            __syncthreads();
            if (warp_n == nc) {
                #pragma unroll
                for (int mf = 0; mf < 4; mf++) {
                    int mloc = warp_m * 64 + mf * 16 + g;
                    #pragma unroll
                    for (int nf = 0; nf < 4; nf++) {
                        int d = nf * 8 + w * 2;
                        Ts[mloc * 33 + d]           = acc[mf][nf][0];
                        Ts[mloc * 33 + d + 1]       = acc[mf][nf][1];
                        Ts[(mloc + 8) * 33 + d]     = acc[mf][nf][2];
                        Ts[(mloc + 8) * 33 + d + 1] = acc[mf][nf][3];
                    }
                }
            }
            __syncthreads();
            #pragma unroll
            for (int dd = 0; dd < 4; dd++) {
                int d = wid * 4 + dd;
                float4 v;
                v.x = tf32rf(Ts[(lane * 4 + 0) * 33 + d]);
                v.y = tf32rf(Ts[(lane * 4 + 1) * 33 + d]);
                v.z = tf32rf(Ts[(lane * 4 + 2) * 33 + d]);
                v.w = tf32rf(Ts[(lane * 4 + 3) * 33 + d]);
                *(float4*)&Cb[(long long)(n0 + nc * 32 + d) * SS + srow0 + lane * 4] = v;
            }
        }
    }
}

// ================= causal softmax (in place, tf32-rounded, zero-fills diagonal band) =================
__device__ __forceinline__ float warpMax(float v) {
    #pragma unroll
    for (int o = 16; o; o >>= 1) v = fmaxf(v, __shfl_xor_sync(0xffffffffu, v, o));
    return v;
}
__device__ __forceinline__ float warpSum(float v) {
    #pragma unroll
    for (int o = 16; o; o >>= 1) v += __shfl_xor_sync(0xffffffffu, v, o);
    return v;
}

__global__ void __launch_bounds__(256) softmax_causal(float* __restrict__ Sc)
{
    int q = blockIdx.x;
    int b = blockIdx.y;
    float* row = Sc + ((long long)b * SS + q) * SS;
    int L = q + 1;
    int tid = threadIdx.x, warp = tid >> 5, lane = tid & 31;
    __shared__ float red[8];

    float m = -1e30f;
    for (int j = tid; j < L; j += 256) m = fmaxf(m, row[j]);
    m = warpMax(m);
    if (lane == 0) red[warp] = m;
    __syncthreads();
    m = (lane < 8) ? red[lane] : -1e30f;
    m = warpMax(m);
    m = __shfl_sync(0xffffffffu, m, 0);

    float sum = 0.f;
    for (int j = tid; j < L; j += 256) {
        float e = __expf(row[j] - m);
        row[j] = e;
        sum += e;
    }
    sum = warpSum(sum);
    __syncthreads();
    if (lane == 0) red[warp] = sum;
    __syncthreads();
    sum = (lane < 8) ? red[lane] : 0.f;
    sum = warpSum(sum);
    sum = __shfl_sync(0xffffffffu, sum, 0);
    float inv = 1.f / sum;

    for (int j = tid; j < L; j += 256) row[j] = tf32rf(row[j] * inv);
    // PV reads only k < (q/128+1)*128 for this row's tile: zero just that band
    int zend = min(SS, ((q >> 7) + 1) << 7);
    for (int j = L + tid; j < zend; j += 256) row[j] = 0.f;
}

// ================= launch =================
extern "C" void kernel_launch(void* const* d_in, const int* in_sizes, int n_in,
                              void* d_out, int out_size)
{
    const float* x   = (const float*)d_in[0];
    const float* Wq  = (const float*)d_in[1];
    const float* Wk  = (const float*)d_in[2];
    const float* Wv  = (const float*)d_in[3];
    const float* Wo  = (const float*)d_in[4];
    const int*   pos = (const int*)d_in[5];
    float* out = (float*)d_out;

    static float *pX=nullptr,*pWq,*pWk,*pWv,*pWo,*pQ,*pK,*pVt,*pS,*pA;
    static bool inited = false;
    if (!inited) {
        cudaGetSymbolAddress((void**)&pX,  g_X);
        cudaGetSymbolAddress((void**)&pWq, g_Wq);
        cudaGetSymbolAddress((void**)&pWk, g_Wk);
        cudaGetSymbolAddress((void**)&pWv, g_Wv);
        cudaGetSymbolAddress((void**)&pWo, g_Wo);
        cudaGetSymbolAddress((void**)&pQ,  g_Q);
        cudaGetSymbolAddress((void**)&pK,  g_K);
        cudaGetSymbolAddress((void**)&pVt, g_Vt);
        cudaGetSymbolAddress((void**)&pS,  g_S);
        cudaGetSymbolAddress((void**)&pA,  g_A);
        cudaFuncSetAttribute(gemm_mma, cudaFuncAttributeMaxDynamicSharedMemorySize, SM_TOTAL);
        inited = true;
    }

    // 1) pre-round x and weights to tf32
    long long tot4 = NX4 + 4LL * NW4;
    preround_all<<<(unsigned)((tot4 + 255) / 256), 256>>>(
        (const float4*)x, (const float4*)Wq, (const float4*)Wk, (const float4*)Wv, (const float4*)Wo,
        (float4*)pX, (float4*)pWq, (float4*)pWk, (float4*)pWv, (float4*)pWo);

    dim3 blk(256);
    dim3 gProj(DD / 128, MM / 128, 1);      // (8, 64)

    // 2-3) Q, K projections with fused RoPE (rounded outputs)
    gemm_mma<<<gProj, blk, SM_TOTAL>>>(pX, pWq, pQ, MM, DD, DD, 0, 0, 0, 1.f, 4, pos);
    gemm_mma<<<gProj, blk, SM_TOTAL>>>(pX, pWk, pK, MM, DD, DD, 0, 0, 0, 1.f, 4, pos);
    // 4) V projection, output transposed per batch -> Vt[b][d][s] (rounded)
    gemm_mma<<<gProj, blk, SM_TOTAL>>>(pX, pWv, pVt, MM, DD, DD, 0, 0, (long long)DD * SS, 1.f, 3, nullptr);

    // 5) scores = Q @ K^T / 32 (causal tile-skip; captured by ncu)
    dim3 gS(SS / 128, SS / 128, BB);        // (16, 16, 4)
    gemm_mma<<<gS, blk, SM_TOTAL>>>(pQ, pK, pS, SS, SS, DD,
                                    (long long)SS * DD, (long long)SS * DD, (long long)SS * SS,
                                    0.03125f, 1, nullptr);

    // 6) causal softmax (rounds probs, zero-fills diagonal band only)
    softmax_causal<<<dim3(SS, BB), 256>>>(pS);

    // 7) attn = P @ Vt^T (K-trunc at diagonal, rounded output)
    dim3 gPV(DD / 128, SS / 128, BB);       // (8, 16, 4)
    gemm_mma<<<gPV, blk, SM_TOTAL>>>(pS, pVt, pA, SS, DD, SS,
                                     (long long)SS * SS, (long long)DD * SS, (long long)SS * DD,
                                     1.f, 2, nullptr);

    // 8) out = attn @ Wo^T (full fp32 output)
    gemm_mma<<<gProj, blk, SM_TOTAL>>>(pA, pWo, out, MM, DD, DD, 0, 0, 0, 1.f, 0, nullptr);
}

// round 7
// speedup vs baseline: 2.0570x; 2.0570x over previous
#include <cuda_runtime.h>
#include <cuda_fp16.h>
#include <math.h>
#include <stdint.h>

// Problem shape (fixed)
#define BB 4
#define SS 2048
#define DD 1024
#define MM (BB*SS)   // 8192

// ---------------- scratch (half precision intermediates) ----------------
__device__ __half g_X [MM*DD];
__device__ __half g_Wq[DD*DD];
__device__ __half g_Wk[DD*DD];
__device__ __half g_Wv[DD*DD];
__device__ __half g_Wo[DD*DD];
__device__ __half g_Q [MM*DD];
__device__ __half g_K [MM*DD];
__device__ __half g_Vt[MM*DD];                 // V transposed per batch: [b][d][s]
__device__ __half g_S [(long long)BB*SS*SS];   // scores / probs
__device__ __half g_A [MM*DD];

// ---------------- helpers ----------------
__device__ __forceinline__ uint32_t smem_u32(const void* p) {
    uint32_t a;
    asm("{ .reg .u64 t; cvta.to.shared.u64 t, %1; cvt.u32.u64 %0, t; }" : "=r"(a) : "l"(p));
    return a;
}
__device__ __forceinline__ void cp16(uint32_t dst, const void* src) {
    asm volatile("cp.async.cg.shared.global [%0], [%1], 16;" :: "r"(dst), "l"(src));
}
#define CP_COMMIT() asm volatile("cp.async.commit_group;" ::: "memory")
#define CP_WAIT1()  asm volatile("cp.async.wait_group 1;"  ::: "memory")

// chunk-swizzled smem offset: row stride 64B, 16B chunk rotated by row>>1 (R5-proven)
#define SWOFF(row, c) ((uint32_t)((row)*64 + ((((c) + ((row)>>1)) & 3) << 4)))

__device__ __forceinline__ uint32_t lds32(const char* p, int row, int c, int w) {
    return ((const uint32_t*)(p + SWOFF(row, c)))[w];
}

// fp16 MMA m16n8k16, fp32 accumulate
#define MMA_F16(cc, a0, a1, a2, a3, b0, b1) \
    asm volatile("mma.sync.aligned.m16n8k16.row.col.f32.f16.f16.f32 " \
        "{%0,%1,%2,%3}, {%4,%5,%6,%7}, {%8,%9}, {%0,%1,%2,%3};" \
        : "+f"((cc)[0]), "+f"((cc)[1]), "+f"((cc)[2]), "+f"((cc)[3]) \
        : "r"(a0), "r"(a1), "r"(a2), "r"(a3), "r"(b0), "r"(b1))

// ================= convert x and all weights to half =================
#define NX4 (MM*DD/4)      // 2097152
#define NW4 (DD*DD/4)      // 262144
__global__ void __launch_bounds__(256) preconv_all(
    const float4* __restrict__ x,
    const float4* __restrict__ wq, const float4* __restrict__ wk,
    const float4* __restrict__ wv, const float4* __restrict__ wo,
    __half* __restrict__ dx,
    __half* __restrict__ dwq, __half* __restrict__ dwk,
    __half* __restrict__ dwv, __half* __restrict__ dwo)
{
    long long i = (long long)blockIdx.x * blockDim.x + threadIdx.x;
    const float4* s; __half* d; long long off;
    if (i < NX4) { s = x; d = dx; off = i; }
    else {
        long long j = i - NX4;
        int seg = (int)(j / NW4);
        off = j % NW4;
        s = seg == 0 ? wq : seg == 1 ? wk : seg == 2 ? wv : wo;
        d = seg == 0 ? dwq : seg == 1 ? dwk : seg == 2 ? dwv : dwo;
    }
    float4 v = s[off];
    __half2 h01 = __floats2half2_rn(v.x, v.y);
    __half2 h23 = __floats2half2_rn(v.z, v.w);
    uint2 u;
    u.x = *reinterpret_cast<uint32_t*>(&h01);
    u.y = *reinterpret_cast<uint32_t*>(&h23);
    *reinterpret_cast<uint2*>(d + off * 4) = u;
}

// ================= fp16 mma GEMM: C = alpha * A @ B^T (TN) =================
// A: M x K half row-major, B: N x K half row-major.
// 128x128 CTA tile, BK=32 halves (64B rows), 3-stage cp.async,
// 256 threads = 8 warps (2x4), warp tile 64x32, m16n8k16 MMAs.
// mode: 0 fp32 out (Wo) | 1 causal tile-skip, half out (scores)
//       | 2 causal K-trunc, half out (PV) | 3 transposed half out (Vt)
//       | 4 fused RoPE, half out (Q/K proj)
#define STAGE 16384           // A 8KB + B 8KB
#define SM_TOTAL (3*STAGE)    // 49152

__global__ void __launch_bounds__(256, 2) gemm_h(
    const __half* __restrict__ A, const __half* __restrict__ B, void* __restrict__ Cv,
    int M, int N, int K,
    long long sA, long long sB, long long sC,
    float alpha, int mode, const int* __restrict__ pos)
{
    extern __shared__ char smem[];
    int bz = blockIdx.z;
    const __half* Ab = A + (long long)bz * sA;
    const __half* Bb = B + (long long)bz * sB;

    int m0 = blockIdx.y * 128;
    int n0 = blockIdx.x * 128;
    if (mode == 1 && n0 >= m0 + 128) return;
    int Keff  = (mode == 2) ? min(K, m0 + 128) : K;
    int nIter = Keff >> 5;                 // BK = 32 halves

    int tid = threadIdx.x, wid = tid >> 5, lane = tid & 31;
    int warp_m = wid >> 2, warp_n = wid & 3;
    int g = lane >> 2, w = lane & 3;
    uint32_t sb = smem_u32(smem);

    // global->smem: thread -> row tid>>1, chunk pair (tid&1)*2, +1 (8 halves per chunk)
    int rowL = tid >> 1, cL = (tid & 1) * 2;
    uint32_t dOff0 = SWOFF(rowL, cL);
    uint32_t dOff1 = SWOFF(rowL, cL + 1);
    const __half* gAp = Ab + (long long)(m0 + rowL) * K + cL * 8;
    const __half* gBp = Bb + (long long)(n0 + rowL) * K + cL * 8;

    float acc[4][4][4];
    #pragma unroll
    for (int i = 0; i < 4; i++)
        #pragma unroll
        for (int j = 0; j < 4; j++)
            #pragma unroll
            for (int q = 0; q < 4; q++) acc[i][j][q] = 0.f;

    #pragma unroll
    for (int s = 0; s < 2; s++) {
        uint32_t base = sb + s * STAGE;
        int k0 = s * 32;
        cp16(base + dOff0,        gAp + k0);
        cp16(base + dOff1,        gAp + k0 + 8);
        cp16(base + 8192 + dOff0, gBp + k0);
        cp16(base + 8192 + dOff1, gBp + k0 + 8);
        CP_COMMIT();
    }

    for (int kt = 0; kt < nIter; kt++) {
        CP_WAIT1();
        __syncthreads();

        const char* pA = smem + (kt % 3) * STAGE;
        const char* pB = pA + 8192;
        #pragma unroll
        for (int ks = 0; ks < 2; ks++) {           // each ks = 16 k-depth
            int c0 = ks * 2;
            uint32_t af[4][4], bf[4][2];
            #pragma unroll
            for (int mf = 0; mf < 4; mf++) {
                int r = warp_m * 64 + mf * 16 + g;
                af[mf][0] = lds32(pA, r,     c0,     w);
                af[mf][1] = lds32(pA, r + 8, c0,     w);
                af[mf][2] = lds32(pA, r,     c0 + 1, w);
                af[mf][3] = lds32(pA, r + 8, c0 + 1, w);
            }
            #pragma unroll
            for (int nf = 0; nf < 4; nf++) {
                int nr = warp_n * 32 + nf * 8 + g;
                bf[nf][0] = lds32(pB, nr, c0,     w);
                bf[nf][1] = lds32(pB, nr, c0 + 1, w);
            }
            #pragma unroll
            for (int mf = 0; mf < 4; mf++)
                #pragma unroll
                for (int nf = 0; nf < 4; nf++)
                    MMA_F16(acc[mf][nf], af[mf][0], af[mf][1], af[mf][2], af[mf][3],
                            bf[nf][0], bf[nf][1]);
        }

        int nk = kt + 2;
        if (nk < nIter) {
            uint32_t base = sb + (nk % 3) * STAGE;
            int k0 = nk * 32;
            cp16(base + dOff0,        gAp + k0);
            cp16(base + dOff1,        gAp + k0 + 8);
            cp16(base + 8192 + dOff0, gBp + k0);
            cp16(base + 8192 + dOff1, gBp + k0 + 8);
        }
        CP_COMMIT();
    }

    if (mode == 0) {
        float* Cb = (float*)Cv + (long long)bz * sC;
        #pragma unroll
        for (int mf = 0; mf < 4; mf++) {
            int r0 = m0 + warp_m * 64 + mf * 16 + g;
            #pragma unroll
            for (int nf = 0; nf < 4; nf++) {
                int col = n0 + warp_n * 32 + nf * 8 + w * 2;
                *(float2*)&Cb[(long long)r0 * N + col] =
                    make_float2(acc[mf][nf][0], acc[mf][nf][1]);
                *(float2*)&Cb[(long long)(r0 + 8) * N + col] =
                    make_float2(acc[mf][nf][2], acc[mf][nf][3]);
            }
        }
    } else if (mode == 4) {
        // fused RoPE epilogue: col pairs (2i, 2i+1) in one half2
        __half* Cb = (__half*)Cv;
        bool is64 = (pos[1] == 0);
        #pragma unroll
        for (int mf = 0; mf < 4; mf++) {
            int r0 = m0 + warp_m * 64 + mf * 16 + g;
            int p0 = is64 ? pos[2 * r0] : pos[r0];
            int p1 = is64 ? pos[2 * (r0 + 8)] : pos[r0 + 8];
            #pragma unroll
            for (int nf = 0; nf < 4; nf++) {
                int col = n0 + warp_n * 32 + nf * 8 + w * 2;
                float inv_freq = exp2f((float)col * (-13.28771238f / (float)DD));
                float c0, s0, c1, s1;
                sincosf((float)p0 * inv_freq, &s0, &c0);
                sincosf((float)p1 * inv_freq, &s1, &c1);
                float x1 = acc[mf][nf][0], x2 = acc[mf][nf][1];
                float y1 = acc[mf][nf][2], y2 = acc[mf][nf][3];
                __half2 v0 = __floats2half2_rn(x1 * c0 - x2 * s0, x1 * s0 + x2 * c0);
                __half2 v1 = __floats2half2_rn(y1 * c1 - y2 * s1, y1 * s1 + y2 * c1);
                *(__half2*)&Cb[(long long)r0 * N + col]       = v0;
                *(__half2*)&Cb[(long long)(r0 + 8) * N + col] = v1;
            }
        }
    } else if (mode != 3) {
        // half output, optional alpha (scores: 1/32; PV: 1)
        __half* Cb = (__half*)Cv + (long long)bz * sC;
        #pragma unroll
        for (int mf = 0; mf < 4; mf++) {
            int r0 = m0 + warp_m * 64 + mf * 16 + g;
            #pragma unroll
            for (int nf = 0; nf < 4; nf++) {
                int col = n0 + warp_n * 32 + nf * 8 + w * 2;
                __half2 v0 = __floats2half2_rn(acc[mf][nf][0] * alpha, acc[mf][nf][1] * alpha);
                __half2 v1 = __floats2half2_rn(acc[mf][nf][2] * alpha, acc[mf][nf][3] * alpha);
                *(__half2*)&Cb[(long long)r0 * N + col]       = v0;
                *(__half2*)&Cb[(long long)(r0 + 8) * N + col] = v1;
            }
        }
    } else {
        // transposed epilogue: stage 128x32 fp32 block through smem, store half d-major
        float* Ts = (float*)smem;                 // [128][33]
        int b = m0 / SS;
        int srow0 = m0 % SS;
        __half* Cb = (__half*)Cv + (long long)b * sC;   // sC = DD*SS
        #pragma unroll
        for (int nc = 0; nc < 4; nc++) {
            __syncthreads();
            if (warp_n == nc) {
                #pragma unroll
                for (int mf = 0; mf < 4; mf++) {
                    int mloc = warp_m * 64 + mf * 16 + g;
                    #pragma unroll
                    for (int nf = 0; nf < 4; nf++) {
                        int d = nf * 8 + w * 2;
                        Ts[mloc * 33 + d]           = acc[mf][nf][0];
                        Ts[mloc * 33 + d + 1]       = acc[mf][nf][1];
                        Ts[(mloc + 8) * 33 + d]     = acc[mf][nf][2];
                        Ts[(mloc + 8) * 33 + d + 1] = acc[mf][nf][3];
                    }
                }
            }
            __syncthreads();
            #pragma unroll
            for (int dd = 0; dd < 4; dd++) {
                int d = wid * 4 + dd;
                __half2 h01 = __floats2half2_rn(Ts[(lane*4+0)*33 + d], Ts[(lane*4+1)*33 + d]);
                __half2 h23 = __floats2half2_rn(Ts[(lane*4+2)*33 + d], Ts[(lane*4+3)*33 + d]);
                uint2 u;
                u.x = *reinterpret_cast<uint32_t*>(&h01);
                u.y = *reinterpret_cast<uint32_t*>(&h23);
                *reinterpret_cast<uint2*>(&Cb[(long long)(n0 + nc*32 + d) * SS + srow0 + lane*4]) = u;
            }
        }
    }
}

// ================= causal softmax (half in/out, fp32 math, zero diagonal band) =================
__device__ __forceinline__ float warpMax(float v) {
    #pragma unroll
    for (int o = 16; o; o >>= 1) v = fmaxf(v, __shfl_xor_sync(0xffffffffu, v, o));
    return v;
}
__device__ __forceinline__ float warpSum(float v) {
    #pragma unroll
    for (int o = 16; o; o >>= 1) v += __shfl_xor_sync(0xffffffffu, v, o);
    return v;
}

__global__ void __launch_bounds__(256) softmax_causal(__half* __restrict__ Sc)
{
    int q = blockIdx.x;
    int b = blockIdx.y;
    __half* row = Sc + ((long long)b * SS + q) * SS;
    int L = q + 1;
    int tid = threadIdx.x, warp = tid >> 5, lane = tid & 31;
    __shared__ float red[8];

    float m = -1e30f;
    for (int j = tid; j < L; j += 256) m = fmaxf(m, __half2float(row[j]));
    m = warpMax(m);
    if (lane == 0) red[warp] = m;
    __syncthreads();
    m = (lane < 8) ? red[lane] : -1e30f;
    m = warpMax(m);
    m = __shfl_sync(0xffffffffu, m, 0);

    float sum = 0.f;
    for (int j = tid; j < L; j += 256) sum += __expf(__half2float(row[j]) - m);
    sum = warpSum(sum);
    __syncthreads();
    if (lane == 0) red[warp] = sum;
    __syncthreads();
    sum = (lane < 8) ? red[lane] : 0.f;
    sum = warpSum(sum);
    sum = __shfl_sync(0xffffffffu, sum, 0);
    float inv = 1.f / sum;

    for (int j = tid; j < L; j += 256)
        row[j] = __float2half(__expf(__half2float(row[j]) - m) * inv);
    // PV reads only k < (q/128+1)*128: zero just the diagonal band tail
    int zend = min(SS, ((q >> 7) + 1) << 7);
    for (int j = L + tid; j < zend; j += 256) row[j] = __float2half(0.f);
}

// ================= launch =================
extern "C" void kernel_launch(void* const* d_in, const int* in_sizes, int n_in,
                              void* d_out, int out_size)
{
    const float* x   = (const float*)d_in[0];
    const float* Wq  = (const float*)d_in[1];
    const float* Wk  = (const float*)d_in[2];
    const float* Wv  = (const float*)d_in[3];
    const float* Wo  = (const float*)d_in[4];
    const int*   pos = (const int*)d_in[5];
    float* out = (float*)d_out;

    static __half *pX=nullptr,*pWq,*pWk,*pWv,*pWo,*pQ,*pK,*pVt,*pS,*pA;
    static bool inited = false;
    if (!inited) {
        cudaGetSymbolAddress((void**)&pX,  g_X);
        cudaGetSymbolAddress((void**)&pWq, g_Wq);
        cudaGetSymbolAddress((void**)&pWk, g_Wk);
        cudaGetSymbolAddress((void**)&pWv, g_Wv);
        cudaGetSymbolAddress((void**)&pWo, g_Wo);
        cudaGetSymbolAddress((void**)&pQ,  g_Q);
        cudaGetSymbolAddress((void**)&pK,  g_K);
        cudaGetSymbolAddress((void**)&pVt, g_Vt);
        cudaGetSymbolAddress((void**)&pS,  g_S);
        cudaGetSymbolAddress((void**)&pA,  g_A);
        cudaFuncSetAttribute(gemm_h, cudaFuncAttributeMaxDynamicSharedMemorySize, SM_TOTAL);
        inited = true;
    }

    // 1) convert x and weights to half
    long long tot4 = NX4 + 4LL * NW4;
    preconv_all<<<(unsigned)((tot4 + 255) / 256), 256>>>(
        (const float4*)x, (const float4*)Wq, (const float4*)Wk, (const float4*)Wv, (const float4*)Wo,
        pX, pWq, pWk, pWv, pWo);

    dim3 blk(256);
    dim3 gProj(DD / 128, MM / 128, 1);      // (8, 64)

    // 2-3) Q, K projections with fused RoPE (half out)
    gemm_h<<<gProj, blk, SM_TOTAL>>>(pX, pWq, pQ, MM, DD, DD, 0, 0, 0, 1.f, 4, pos);
    gemm_h<<<gProj, blk, SM_TOTAL>>>(pX, pWk, pK, MM, DD, DD, 0, 0, 0, 1.f, 4, pos);
    // 4) V projection, transposed per batch -> Vt[b][d][s] (half)
    gemm_h<<<gProj, blk, SM_TOTAL>>>(pX, pWv, pVt, MM, DD, DD, 0, 0, (long long)DD * SS, 1.f, 3, nullptr);

    // 5) scores = Q @ K^T / 32 (causal tile-skip, half out)
    dim3 gS(SS / 128, SS / 128, BB);        // (16, 16, 4)
    gemm_h<<<gS, blk, SM_TOTAL>>>(pQ, pK, pS, SS, SS, DD,
                                  (long long)SS * DD, (long long)SS * DD, (long long)SS * SS,
                                  0.03125f, 1, nullptr);

    // 6) causal softmax (half in/out, zero diagonal band)
    softmax_causal<<<dim3(SS, BB), 256>>>(pS);

    // 7) attn = P @ Vt^T (K-trunc at diagonal, half out)
    dim3 gPV(DD / 128, SS / 128, BB);       // (8, 16, 4)
    gemm_h<<<gPV, blk, SM_TOTAL>>>(pS, pVt, pA, SS, DD, SS,
                                   (long long)SS * SS, (long long)DD * SS, (long long)SS * DD,
                                   1.f, 2, nullptr);

    // 8) out = attn @ Wo^T (fp32 output)
    gemm_h<<<gProj, blk, SM_TOTAL>>>(pA, pWo, out, MM, DD, DD, 0, 0, 0, 1.f, 0, nullptr);
}

// round 8
// speedup vs baseline: 2.3195x; 1.1276x over previous
#include <cuda_runtime.h>
#include <cuda_fp16.h>
#include <math.h>
#include <stdint.h>

// Problem shape (fixed)
#define BB 4
#define SS 2048
#define DD 1024
#define MM (BB*SS)   // 8192

// ---------------- scratch (half precision intermediates) ----------------
__device__ __half g_X [MM*DD];
__device__ __half g_Wq[DD*DD];
__device__ __half g_Wk[DD*DD];
__device__ __half g_Wv[DD*DD];
__device__ __half g_Wo[DD*DD];
__device__ __half g_Q [MM*DD];
__device__ __half g_K [MM*DD];
__device__ __half g_Vt[MM*DD];                 // V transposed per batch: [b][d][s]
__device__ __half g_S [(long long)BB*SS*SS];   // scores / probs
__device__ __half g_A [MM*DD];

// ---------------- helpers ----------------
__device__ __forceinline__ uint32_t smem_u32(const void* p) {
    uint32_t a;
    asm("{ .reg .u64 t; cvta.to.shared.u64 t, %1; cvt.u32.u64 %0, t; }" : "=r"(a) : "l"(p));
    return a;
}
__device__ __forceinline__ void cp16(uint32_t dst, const void* src) {
    asm volatile("cp.async.cg.shared.global [%0], [%1], 16;" :: "r"(dst), "l"(src));
}
#define CP_COMMIT() asm volatile("cp.async.commit_group;" ::: "memory")
#define CP_WAIT1()  asm volatile("cp.async.wait_group 1;"  ::: "memory")

// chunk-swizzled smem offset: row stride 64B, 16B chunk rotated by row>>1 (proven layout)
#define SWOFF(row, c) ((uint32_t)((row)*64 + ((((c) + ((row)>>1)) & 3) << 4)))
// identity: SWOFF(row, c+2) == SWOFF(row, c) ^ 0x20

__device__ __forceinline__ void ldsm_x4(uint32_t& r0, uint32_t& r1, uint32_t& r2, uint32_t& r3,
                                        uint32_t addr) {
    asm volatile("ldmatrix.sync.aligned.m8n8.x4.shared.b16 {%0,%1,%2,%3}, [%4];"
                 : "=r"(r0), "=r"(r1), "=r"(r2), "=r"(r3) : "r"(addr));
}

// fp16 MMA m16n8k16, fp32 accumulate
#define MMA_F16(cc, a0, a1, a2, a3, b0, b1) \
    asm volatile("mma.sync.aligned.m16n8k16.row.col.f32.f16.f16.f32 " \
        "{%0,%1,%2,%3}, {%4,%5,%6,%7}, {%8,%9}, {%0,%1,%2,%3};" \
        : "+f"((cc)[0]), "+f"((cc)[1]), "+f"((cc)[2]), "+f"((cc)[3]) \
        : "r"(a0), "r"(a1), "r"(a2), "r"(a3), "r"(b0), "r"(b1))

// ================= convert x and all weights to half =================
#define NX4 (MM*DD/4)      // 2097152
#define NW4 (DD*DD/4)      // 262144
__global__ void __launch_bounds__(256) preconv_all(
    const float4* __restrict__ x,
    const float4* __restrict__ wq, const float4* __restrict__ wk,
    const float4* __restrict__ wv, const float4* __restrict__ wo,
    __half* __restrict__ dx,
    __half* __restrict__ dwq, __half* __restrict__ dwk,
    __half* __restrict__ dwv, __half* __restrict__ dwo)
{
    long long i = (long long)blockIdx.x * blockDim.x + threadIdx.x;
    const float4* s; __half* d; long long off;
    if (i < NX4) { s = x; d = dx; off = i; }
    else {
        long long j = i - NX4;
        int seg = (int)(j / NW4);
        off = j % NW4;
        s = seg == 0 ? wq : seg == 1 ? wk : seg == 2 ? wv : wo;
        d = seg == 0 ? dwq : seg == 1 ? dwk : seg == 2 ? dwv : dwo;
    }
    float4 v = s[off];
    __half2 h01 = __floats2half2_rn(v.x, v.y);
    __half2 h23 = __floats2half2_rn(v.z, v.w);
    uint2 u;
    u.x = *reinterpret_cast<uint32_t*>(&h01);
    u.y = *reinterpret_cast<uint32_t*>(&h23);
    *reinterpret_cast<uint2*>(d + off * 4) = u;
}

// ================= fp16 mma GEMM: C = alpha * A @ B^T (TN) =================
// 128x128 CTA tile, BK=32 halves, 3-stage cp.async, 256 threads = 8 warps (2x4),
// warp tile 64x32, ldmatrix.x4 fragment loads, m16n8k16 MMAs.
// mode: 0 fp32 out (Wo) | 1 causal tile-skip, half out (scores)
//       | 2 causal K-trunc, half out (PV) | 3 transposed half out (Vt)
//       | 4 fused RoPE, half out (Q/K proj)
#define STAGE 16384           // A 8KB + B 8KB
#define SM_TOTAL (3*STAGE)    // 49152

__global__ void __launch_bounds__(256, 2) gemm_h(
    const __half* __restrict__ A, const __half* __restrict__ B, void* __restrict__ Cv,
    int M, int N, int K,
    long long sA, long long sB, long long sC,
    float alpha, int mode, const int* __restrict__ pos)
{
    extern __shared__ char smem[];
    int bz = blockIdx.z;
    const __half* Ab = A + (long long)bz * sA;
    const __half* Bb = B + (long long)bz * sB;

    int m0 = blockIdx.y * 128;
    int n0 = blockIdx.x * 128;
    if (mode == 1 && n0 >= m0 + 128) return;
    int Keff  = (mode == 2) ? min(K, m0 + 128) : K;
    int nIter = Keff >> 5;                 // BK = 32 halves

    int tid = threadIdx.x, wid = tid >> 5, lane = tid & 31;
    int warp_m = wid >> 2, warp_n = wid & 3;
    int g = lane >> 2, w = lane & 3;
    uint32_t sb = smem_u32(smem);

    // ---- ldmatrix per-lane offsets (ks=0); ks=1 = XOR 0x20 ----
    int lr8 = lane & 7;
    uint32_t aOff[4], bOff[2];
    {
        int arow = warp_m * 64 + lr8 + ((lane >> 3) & 1) * 8;   // + mf*16 added below
        int ach  = lane >> 4;                                    // chunk 0 or 1
        #pragma unroll
        for (int mf = 0; mf < 4; mf++) aOff[mf] = SWOFF(arow + mf * 16, ach);
        int j = lane >> 3;
        #pragma unroll
        for (int p = 0; p < 2; p++) {
            int brow = warp_n * 32 + (2 * p + (j >> 1)) * 8 + lr8;
            int bch  = j & 1;
            bOff[p] = SWOFF(brow, bch);
        }
    }

    // global->smem: thread -> row tid>>1, chunk pair (tid&1)*2, +1 (8 halves per chunk)
    int rowL = tid >> 1, cL = (tid & 1) * 2;
    uint32_t dOff0 = SWOFF(rowL, cL);
    uint32_t dOff1 = SWOFF(rowL, cL + 1);
    const __half* gAp = Ab + (long long)(m0 + rowL) * K + cL * 8;
    const __half* gBp = Bb + (long long)(n0 + rowL) * K + cL * 8;

    float acc[4][4][4];
    #pragma unroll
    for (int i = 0; i < 4; i++)
        #pragma unroll
        for (int j2 = 0; j2 < 4; j2++)
            #pragma unroll
            for (int q = 0; q < 4; q++) acc[i][j2][q] = 0.f;

    #pragma unroll
    for (int s = 0; s < 2; s++) {
        uint32_t base = sb + s * STAGE;
        int k0 = s * 32;
        cp16(base + dOff0,        gAp + k0);
        cp16(base + dOff1,        gAp + k0 + 8);
        cp16(base + 8192 + dOff0, gBp + k0);
        cp16(base + 8192 + dOff1, gBp + k0 + 8);
        CP_COMMIT();
    }

    for (int kt = 0; kt < nIter; kt++) {
        CP_WAIT1();
        __syncthreads();

        uint32_t baseA = sb + (kt % 3) * STAGE;
        uint32_t baseB = baseA + 8192;
        #pragma unroll
        for (int ks = 0; ks < 2; ks++) {           // each ks = 16 k-depth
            uint32_t xo = ks ? 0x20u : 0u;
            uint32_t af[4][4], bf[4][2];
            #pragma unroll
            for (int mf = 0; mf < 4; mf++)
                ldsm_x4(af[mf][0], af[mf][1], af[mf][2], af[mf][3], baseA + (aOff[mf] ^ xo));
            ldsm_x4(bf[0][0], bf[0][1], bf[1][0], bf[1][1], baseB + (bOff[0] ^ xo));
            ldsm_x4(bf[2][0], bf[2][1], bf[3][0], bf[3][1], baseB + (bOff[1] ^ xo));
            #pragma unroll
            for (int mf = 0; mf < 4; mf++)
                #pragma unroll
                for (int nf = 0; nf < 4; nf++)
                    MMA_F16(acc[mf][nf], af[mf][0], af[mf][1], af[mf][2], af[mf][3],
                            bf[nf][0], bf[nf][1]);
        }

        int nk = kt + 2;
        if (nk < nIter) {
            uint32_t base = sb + (nk % 3) * STAGE;
            int k0 = nk * 32;
            cp16(base + dOff0,        gAp + k0);
            cp16(base + dOff1,        gAp + k0 + 8);
            cp16(base + 8192 + dOff0, gBp + k0);
            cp16(base + 8192 + dOff1, gBp + k0 + 8);
        }
        CP_COMMIT();
    }

    if (mode == 0) {
        float* Cb = (float*)Cv + (long long)bz * sC;
        #pragma unroll
        for (int mf = 0; mf < 4; mf++) {
            int r0 = m0 + warp_m * 64 + mf * 16 + g;
            #pragma unroll
            for (int nf = 0; nf < 4; nf++) {
                int col = n0 + warp_n * 32 + nf * 8 + w * 2;
                *(float2*)&Cb[(long long)r0 * N + col] =
                    make_float2(acc[mf][nf][0], acc[mf][nf][1]);
                *(float2*)&Cb[(long long)(r0 + 8) * N + col] =
                    make_float2(acc[mf][nf][2], acc[mf][nf][3]);
            }
        }
    } else if (mode == 4) {
        // fused RoPE epilogue: col pairs (2i, 2i+1) in one half2
        __half* Cb = (__half*)Cv;
        bool is64 = (pos[1] == 0);
        #pragma unroll
        for (int mf = 0; mf < 4; mf++) {
            int r0 = m0 + warp_m * 64 + mf * 16 + g;
            int p0 = is64 ? pos[2 * r0] : pos[r0];
            int p1 = is64 ? pos[2 * (r0 + 8)] : pos[r0 + 8];
            #pragma unroll
            for (int nf = 0; nf < 4; nf++) {
                int col = n0 + warp_n * 32 + nf * 8 + w * 2;
                float inv_freq = exp2f((float)col * (-13.28771238f / (float)DD));
                float c0, s0, c1, s1;
                sincosf((float)p0 * inv_freq, &s0, &c0);
                sincosf((float)p1 * inv_freq, &s1, &c1);
                float x1 = acc[mf][nf][0], x2 = acc[mf][nf][1];
                float y1 = acc[mf][nf][2], y2 = acc[mf][nf][3];
                __half2 v0 = __floats2half2_rn(x1 * c0 - x2 * s0, x1 * s0 + x2 * c0);
                __half2 v1 = __floats2half2_rn(y1 * c1 - y2 * s1, y1 * s1 + y2 * c1);
                *(__half2*)&Cb[(long long)r0 * N + col]       = v0;
                *(__half2*)&Cb[(long long)(r0 + 8) * N + col] = v1;
            }
        }
    } else if (mode != 3) {
        // half output, optional alpha (scores: 1/32; PV: 1)
        __half* Cb = (__half*)Cv + (long long)bz * sC;
        #pragma unroll
        for (int mf = 0; mf < 4; mf++) {
            int r0 = m0 + warp_m * 64 + mf * 16 + g;
            #pragma unroll
            for (int nf = 0; nf < 4; nf++) {
                int col = n0 + warp_n * 32 + nf * 8 + w * 2;
                __half2 v0 = __floats2half2_rn(acc[mf][nf][0] * alpha, acc[mf][nf][1] * alpha);
                __half2 v1 = __floats2half2_rn(acc[mf][nf][2] * alpha, acc[mf][nf][3] * alpha);
                *(__half2*)&Cb[(long long)r0 * N + col]       = v0;
                *(__half2*)&Cb[(long long)(r0 + 8) * N + col] = v1;
            }
        }
    } else {
        // transposed epilogue: stage 128x32 fp32 block through smem, store half d-major
        float* Ts = (float*)smem;                 // [128][33]
        int b = m0 / SS;
        int srow0 = m0 % SS;
        __half* Cb = (__half*)Cv + (long long)b * sC;   // sC = DD*SS
        #pragma unroll
        for (int nc = 0; nc < 4; nc++) {
            __syncthreads();
            if (warp_n == nc) {
                #pragma unroll
                for (int mf = 0; mf < 4; mf++) {
                    int mloc = warp_m * 64 + mf * 16 + g;
                    #pragma unroll
                    for (int nf = 0; nf < 4; nf++) {
                        int d = nf * 8 + w * 2;
                        Ts[mloc * 33 + d]           = acc[mf][nf][0];
                        Ts[mloc * 33 + d + 1]       = acc[mf][nf][1];
                        Ts[(mloc + 8) * 33 + d]     = acc[mf][nf][2];
                        Ts[(mloc + 8) * 33 + d + 1] = acc[mf][nf][3];
                    }
                }
            }
            __syncthreads();
            #pragma unroll
            for (int dd = 0; dd < 4; dd++) {
                int d = wid * 4 + dd;
                __half2 h01 = __floats2half2_rn(Ts[(lane*4+0)*33 + d], Ts[(lane*4+1)*33 + d]);
                __half2 h23 = __floats2half2_rn(Ts[(lane*4+2)*33 + d], Ts[(lane*4+3)*33 + d]);
                uint2 u;
                u.x = *reinterpret_cast<uint32_t*>(&h01);
                u.y = *reinterpret_cast<uint32_t*>(&h23);
                *reinterpret_cast<uint2*>(&Cb[(long long)(n0 + nc*32 + d) * SS + srow0 + lane*4]) = u;
            }
        }
    }
}

// ================= causal softmax (half in/out, fp32 math, zero diagonal band) =================
__device__ __forceinline__ float warpMax(float v) {
    #pragma unroll
    for (int o = 16; o; o >>= 1) v = fmaxf(v, __shfl_xor_sync(0xffffffffu, v, o));
    return v;
}
__device__ __forceinline__ float warpSum(float v) {
    #pragma unroll
    for (int o = 16; o; o >>= 1) v += __shfl_xor_sync(0xffffffffu, v, o);
    return v;
}

__global__ void __launch_bounds__(256) softmax_causal(__half* __restrict__ Sc)
{
    int q = blockIdx.x;
    int b = blockIdx.y;
    __half* row = Sc + ((long long)b * SS + q) * SS;
    int L = q + 1;
    int tid = threadIdx.x, warp = tid >> 5, lane = tid & 31;
    __shared__ float red[8];

    float m = -1e30f;
    for (int j = tid; j < L; j += 256) m = fmaxf(m, __half2float(row[j]));
    m = warpMax(m);
    if (lane == 0) red[warp] = m;
    __syncthreads();
    m = (lane < 8) ? red[lane] : -1e30f;
    m = warpMax(m);
    m = __shfl_sync(0xffffffffu, m, 0);

    float sum = 0.f;
    for (int j = tid; j < L; j += 256) sum += __expf(__half2float(row[j]) - m);
    sum = warpSum(sum);
    __syncthreads();
    if (lane == 0) red[warp] = sum;
    __syncthreads();
    sum = (lane < 8) ? red[lane] : 0.f;
    sum = warpSum(sum);
    sum = __shfl_sync(0xffffffffu, sum, 0);
    float inv = 1.f / sum;

    for (int j = tid; j < L; j += 256)
        row[j] = __float2half(__expf(__half2float(row[j]) - m) * inv);
    // PV reads only k < (q/128+1)*128: zero just the diagonal band tail
    int zend = min(SS, ((q >> 7) + 1) << 7);
    for (int j = L + tid; j < zend; j += 256) row[j] = __float2half(0.f);
}

// ================= launch =================
extern "C" void kernel_launch(void* const* d_in, const int* in_sizes, int n_in,
                              void* d_out, int out_size)
{
    const float* x   = (const float*)d_in[0];
    const float* Wq  = (const float*)d_in[1];
    const float* Wk  = (const float*)d_in[2];
    const float* Wv  = (const float*)d_in[3];
    const float* Wo  = (const float*)d_in[4];
    const int*   pos = (const int*)d_in[5];
    float* out = (float*)d_out;

    static __half *pX=nullptr,*pWq,*pWk,*pWv,*pWo,*pQ,*pK,*pVt,*pS,*pA;
    static bool inited = false;
    if (!inited) {
        cudaGetSymbolAddress((void**)&pX,  g_X);
        cudaGetSymbolAddress((void**)&pWq, g_Wq);
        cudaGetSymbolAddress((void**)&pWk, g_Wk);
        cudaGetSymbolAddress((void**)&pWv, g_Wv);
        cudaGetSymbolAddress((void**)&pWo, g_Wo);
        cudaGetSymbolAddress((void**)&pQ,  g_Q);
        cudaGetSymbolAddress((void**)&pK,  g_K);
        cudaGetSymbolAddress((void**)&pVt, g_Vt);
        cudaGetSymbolAddress((void**)&pS,  g_S);
        cudaGetSymbolAddress((void**)&pA,  g_A);
        cudaFuncSetAttribute(gemm_h, cudaFuncAttributeMaxDynamicSharedMemorySize, SM_TOTAL);
        inited = true;
    }

    // 1) convert x and weights to half
    long long tot4 = NX4 + 4LL * NW4;
    preconv_all<<<(unsigned)((tot4 + 255) / 256), 256>>>(
        (const float4*)x, (const float4*)Wq, (const float4*)Wk, (const float4*)Wv, (const float4*)Wo,
        pX, pWq, pWk, pWv, pWo);

    dim3 blk(256);
    dim3 gProj(DD / 128, MM / 128, 1);      // (8, 64)

    // 2-3) Q, K projections with fused RoPE (half out)
    gemm_h<<<gProj, blk, SM_TOTAL>>>(pX, pWq, pQ, MM, DD, DD, 0, 0, 0, 1.f, 4, pos);
    gemm_h<<<gProj, blk, SM_TOTAL>>>(pX, pWk, pK, MM, DD, DD, 0, 0, 0, 1.f, 4, pos);
    // 4) V projection, transposed per batch -> Vt[b][d][s] (half)
    gemm_h<<<gProj, blk, SM_TOTAL>>>(pX, pWv, pVt, MM, DD, DD, 0, 0, (long long)DD * SS, 1.f, 3, nullptr);

    // 5) scores = Q @ K^T / 32 (causal tile-skip, half out)
    dim3 gS(SS / 128, SS / 128, BB);        // (16, 16, 4)
    gemm_h<<<gS, blk, SM_TOTAL>>>(pQ, pK, pS, SS, SS, DD,
                                  (long long)SS * DD, (long long)SS * DD, (long long)SS * SS,
                                  0.03125f, 1, nullptr);

    // 6) causal softmax (half in/out, zero diagonal band)
    softmax_causal<<<dim3(SS, BB), 256>>>(pS);

    // 7) attn = P @ Vt^T (K-trunc at diagonal, half out)
    dim3 gPV(DD / 128, SS / 128, BB);       // (8, 16, 4)
    gemm_h<<<gPV, blk, SM_TOTAL>>>(pS, pVt, pA, SS, DD, SS,
                                   (long long)SS * SS, (long long)DD * SS, (long long)SS * DD,
                                   1.f, 2, nullptr);

    // 8) out = attn @ Wo^T (fp32 output)
    gemm_h<<<gProj, blk, SM_TOTAL>>>(pA, pWo, out, MM, DD, DD, 0, 0, 0, 1.f, 0, nullptr);
}